// round 7
// baseline (speedup 1.0000x reference)
#include <cuda_runtime.h>
#include <cuda_bf16.h>
#include <stdint.h>

typedef unsigned int u32;

#define B_    8
#define S_    2048
#define D_    512
#define NROWS 16384
#define QKVW  1536              // fused q|k|v row width

// Tiling
#define TM 64
#define TN 128
#define TK 32

// SMEM layout (bytes)
#define A_STRIDE  80     // 40 bf16 per row (32 data + pad) -> conflict-free LDSM
#define BN_STRIDE 272    // 136 bf16 per row for [K,N] B tiles (32 rows = 8704B)
#define A_BUF     5120   // 64 rows * 80B
#define B_BUF     10240  // 128 rows * 80B (or 32*272 = 8704 for NN)
#define AOFF_LO   5120
#define BOFF_HI   10240
#define BOFF_LO   20480
#define STAGE_SZ  30720          // Ah, Al, Bh, Bl
#define SMEM_DYN  (2*STAGE_SZ)   // double buffered: 60 KB -> 3 CTAs/SM

// ---------------------------------------------------------------------------
// Scratch (static device globals — no runtime allocation)
// ---------------------------------------------------------------------------
__device__ __nv_bfloat16 g_xh[(size_t)NROWS*D_];
__device__ __nv_bfloat16 g_xl[(size_t)NROWS*D_];
__device__ __nv_bfloat16 g_wh[(size_t)4*D_*D_];   // Wq|Wk|Wv|Wd rows
__device__ __nv_bfloat16 g_wl[(size_t)4*D_*D_];
__device__ float         g_bias[QKVW];            // bq|bk|bv packed
__device__ __nv_bfloat16 g_qkvh[(size_t)NROWS*QKVW];
__device__ __nv_bfloat16 g_qkvl[(size_t)NROWS*QKVW];
__device__ __nv_bfloat16 g_yh[(size_t)NROWS*D_];
__device__ __nv_bfloat16 g_yl[(size_t)NROWS*D_];
__device__ float         g_s [(size_t)B_*S_*S_];  // fp32 scores
__device__ __nv_bfloat16 g_ah[(size_t)B_*S_*S_];  // attn hi
__device__ __nv_bfloat16 g_al[(size_t)B_*S_*S_];  // attn lo

// ---------------------------------------------------------------------------
// PTX helpers (portable sm_80-era; legal on base compute_103 target)
// ---------------------------------------------------------------------------
static __device__ __forceinline__ void cpa(u32 dst, const void* src) {
    asm volatile("cp.async.cg.shared.global [%0], [%1], 16;"
                 :: "r"(dst), "l"(src));
}
static __device__ __forceinline__ void ldsm4(u32 &r0,u32 &r1,u32 &r2,u32 &r3, u32 a) {
    asm volatile("ldmatrix.sync.aligned.m8n8.x4.shared.b16 {%0,%1,%2,%3}, [%4];"
                 : "=r"(r0),"=r"(r1),"=r"(r2),"=r"(r3) : "r"(a));
}
static __device__ __forceinline__ void ldsm4t(u32 &r0,u32 &r1,u32 &r2,u32 &r3, u32 a) {
    asm volatile("ldmatrix.sync.aligned.m8n8.x4.trans.shared.b16 {%0,%1,%2,%3}, [%4];"
                 : "=r"(r0),"=r"(r1),"=r"(r2),"=r"(r3) : "r"(a));
}
static __device__ __forceinline__ void mma16816(float* d, const u32* a, const u32* b) {
    asm volatile(
        "mma.sync.aligned.m16n8k16.row.col.f32.bf16.bf16.f32 "
        "{%0,%1,%2,%3}, {%4,%5,%6,%7}, {%8,%9}, {%0,%1,%2,%3};"
        : "+f"(d[0]),"+f"(d[1]),"+f"(d[2]),"+f"(d[3])
        : "r"(a[0]),"r"(a[1]),"r"(a[2]),"r"(a[3]), "r"(b[0]),"r"(b[1]));
}

static __device__ __forceinline__ void split_bf(float x, __nv_bfloat16& h, __nv_bfloat16& l) {
    h = __float2bfloat16(x);
    l = __float2bfloat16(x - __bfloat162float(h));
}
static __device__ __forceinline__ u32 pk(__nv_bfloat16 a, __nv_bfloat16 b) {
    return (u32)__bfloat16_as_ushort(a) | ((u32)__bfloat16_as_ushort(b) << 16);
}

// ---------------------------------------------------------------------------
// bf16x3 HMMA GEMM:  C[m,n] = alpha * sum_k A[m,k]*B(n,k)  (+bias[n])
//   A: [M,K] K-major hi/lo.
//   BNK=true : B is [N,K] K-major (NT gemm) ; BNK=false: B is [K,N] (NN gemm)
//   EPI 0: fp32 out (alpha, optional bias);  EPI 1: split bf16 hi/lo out.
// grid = (N/TN, M/TM, batch), 256 threads, 3 CTAs/SM.
// ---------------------------------------------------------------------------
template <bool BNK, int EPI>
__global__ void __launch_bounds__(256, 3) gemm_k(
    const __nv_bfloat16* __restrict__ Ah, const __nv_bfloat16* __restrict__ Al,
    int lda, size_t abatch,
    const __nv_bfloat16* __restrict__ Bh, const __nv_bfloat16* __restrict__ Bl,
    int ldb, size_t bbatch,
    int K, float alpha, const float* __restrict__ bias,
    float* __restrict__ Cf, __nv_bfloat16* __restrict__ Ch, __nv_bfloat16* __restrict__ Cl,
    int ldc, size_t cbatch)
{
    extern __shared__ __align__(1024) char dsm[];
    const u32 sb   = (u32)__cvta_generic_to_shared(dsm);
    const int tid  = threadIdx.x;
    const int wid  = tid >> 5;
    const int lane = tid & 31;
    const int bm = blockIdx.y, bn = blockIdx.x, bz = blockIdx.z;
    const int warp_m = wid & 1;        // 2 warps along M (32 rows each)
    const int warp_n = wid >> 1;       // 4 warps along N (32 cols each)

    const __nv_bfloat16* pAh = Ah + (size_t)bz*abatch + (size_t)(bm*TM)*lda;
    const __nv_bfloat16* pAl = Al + (size_t)bz*abatch + (size_t)(bm*TM)*lda;
    const __nv_bfloat16* pBh;
    const __nv_bfloat16* pBl;
    if (BNK) {
        pBh = Bh + (size_t)bz*bbatch + (size_t)(bn*TN)*ldb;
        pBl = Bl + (size_t)bz*bbatch + (size_t)(bn*TN)*ldb;
    } else {
        pBh = Bh + (size_t)bz*bbatch + bn*TN;
        pBl = Bl + (size_t)bz*bbatch + bn*TN;
    }

    // ---- stage loader: 6 cp.async (16B) per thread ----
    auto load_stage = [&](int stg, int t) {
        const int k0 = t * TK;
        const u32 da = sb + stg * STAGE_SZ;
        {   // A: 64 rows x 4 chunks
            const int r = tid >> 2, c = tid & 3;
            const u32 d = da + r * A_STRIDE + c * 16;
            cpa(d,           pAh + (size_t)r * lda + k0 + c * 8);
            cpa(d + AOFF_LO, pAl + (size_t)r * lda + k0 + c * 8);
        }
#pragma unroll
        for (int i = 0; i < 2; ++i) {
            const int idx = tid + i * 256;
            if (BNK) {
                const int r = idx >> 2, c = idx & 3;        // 128 rows x 4 chunks
                const u32 db = da + BOFF_HI + r * A_STRIDE + c * 16;
                cpa(db,         pBh + (size_t)r * ldb + k0 + c * 8);
                cpa(db + B_BUF, pBl + (size_t)r * ldb + k0 + c * 8);
            } else {
                const int rb = idx >> 4, cb = idx & 15;     // 32 rows x 16 chunks
                const u32 db = da + BOFF_HI + rb * BN_STRIDE + cb * 16;
                cpa(db,         pBh + (size_t)(k0 + rb) * ldb + cb * 8);
                cpa(db + B_BUF, pBl + (size_t)(k0 + rb) * ldb + cb * 8);
            }
        }
        asm volatile("cp.async.commit_group;");
    };

    // ---- ldmatrix lane offsets (bytes) ----
    const u32 aoff = ((warp_m * 32 + (lane & 15)) * 40 + (lane >> 4) * 8) * 2;
    u32 boff;
    if (BNK)
        boff = ((warp_n * 32 + ((lane >> 4) & 1) * 8 + (lane & 7)) * 40
                + ((lane >> 3) & 1) * 8) * 2;
    else
        boff = ((((lane >> 3) & 1) * 8 + (lane & 7)) * 136
                + warp_n * 32 + ((lane >> 4) & 1) * 8) * 2;

    float acc[2][4][4];
#pragma unroll
    for (int mt = 0; mt < 2; ++mt)
#pragma unroll
        for (int nt = 0; nt < 4; ++nt)
#pragma unroll
            for (int i = 0; i < 4; ++i) acc[mt][nt][i] = 0.f;

    // ---- mainloop compute on one stage (2 k16 steps, hh -> hl -> lh) ----
    auto compute = [&](int stg) {
        const u32 sa = sb + stg * STAGE_SZ;
        const u32 ab = sa + aoff;
        const u32 bb = sa + BOFF_HI + boff;
#pragma unroll
        for (int kk = 0; kk < 2; ++kk) {
            u32 ahf[2][4], bhf[4][2], blf[4][2], alf[2][4];
#pragma unroll
            for (int mt = 0; mt < 2; ++mt)
                ldsm4(ahf[mt][0], ahf[mt][1], ahf[mt][2], ahf[mt][3],
                      ab + mt * (16 * A_STRIDE) + kk * 32);
#pragma unroll
            for (int n2 = 0; n2 < 2; ++n2) {
                u32 r0, r1, r2, r3;
                if (BNK) ldsm4 (r0, r1, r2, r3, bb + n2 * (16 * A_STRIDE) + kk * 32);
                else     ldsm4t(r0, r1, r2, r3, bb + n2 * 32 + kk * (16 * BN_STRIDE));
                bhf[n2*2][0] = r0; bhf[n2*2][1] = r1;
                bhf[n2*2+1][0] = r2; bhf[n2*2+1][1] = r3;
            }
#pragma unroll
            for (int mt = 0; mt < 2; ++mt)
#pragma unroll
                for (int nt = 0; nt < 4; ++nt)
                    mma16816(acc[mt][nt], ahf[mt], bhf[nt]);      // hi*hi

#pragma unroll
            for (int n2 = 0; n2 < 2; ++n2) {
                u32 r0, r1, r2, r3;
                if (BNK) ldsm4 (r0, r1, r2, r3, bb + B_BUF + n2 * (16 * A_STRIDE) + kk * 32);
                else     ldsm4t(r0, r1, r2, r3, bb + B_BUF + n2 * 32 + kk * (16 * BN_STRIDE));
                blf[n2*2][0] = r0; blf[n2*2][1] = r1;
                blf[n2*2+1][0] = r2; blf[n2*2+1][1] = r3;
            }
#pragma unroll
            for (int mt = 0; mt < 2; ++mt)
#pragma unroll
                for (int nt = 0; nt < 4; ++nt)
                    mma16816(acc[mt][nt], ahf[mt], blf[nt]);      // hi*lo

#pragma unroll
            for (int mt = 0; mt < 2; ++mt)
                ldsm4(alf[mt][0], alf[mt][1], alf[mt][2], alf[mt][3],
                      ab + AOFF_LO + mt * (16 * A_STRIDE) + kk * 32);
#pragma unroll
            for (int mt = 0; mt < 2; ++mt)
#pragma unroll
                for (int nt = 0; nt < 4; ++nt)
                    mma16816(acc[mt][nt], alf[mt], bhf[nt]);      // lo*hi
        }
    };

    const int T = K / TK;
    load_stage(0, 0);
    for (int t = 0; t < T; ++t) {
        if (t + 1 < T) {
            load_stage((t + 1) & 1, t + 1);
            asm volatile("cp.async.wait_group 1;");
        } else {
            asm volatile("cp.async.wait_group 0;");
        }
        __syncthreads();
        compute(t & 1);
        __syncthreads();
    }

    // ---- epilogue ----
    const int g  = lane >> 2;
    const int tc = lane & 3;
    const int row_w = bm * TM + warp_m * 32;
    const int col_w = bn * TN + warp_n * 32;
#pragma unroll
    for (int mt = 0; mt < 2; ++mt) {
#pragma unroll
        for (int nt = 0; nt < 4; ++nt) {
            const int r0 = row_w + mt * 16 + g;
            const int c0 = col_w + nt * 8 + tc * 2;
            float v0 = acc[mt][nt][0], v1 = acc[mt][nt][1];
            float v2 = acc[mt][nt][2], v3 = acc[mt][nt][3];
            if constexpr (EPI == 0) {
                v0 *= alpha; v1 *= alpha; v2 *= alpha; v3 *= alpha;
                if (bias) {
                    const float b0 = bias[c0], b1 = bias[c0 + 1];
                    v0 += b0; v1 += b1; v2 += b0; v3 += b1;
                }
                float* base = Cf + (size_t)bz * cbatch;
                *reinterpret_cast<float2*>(base + (size_t)r0 * ldc + c0)       = make_float2(v0, v1);
                *reinterpret_cast<float2*>(base + (size_t)(r0 + 8) * ldc + c0) = make_float2(v2, v3);
            } else {
                if (bias) {
                    const float b0 = bias[c0], b1 = bias[c0 + 1];
                    v0 += b0; v1 += b1; v2 += b0; v3 += b1;
                }
                __nv_bfloat16 h0,l0,h1,l1,h2,l2,h3,l3;
                split_bf(v0,h0,l0); split_bf(v1,h1,l1);
                split_bf(v2,h2,l2); split_bf(v3,h3,l3);
                __nv_bfloat16* dh = Ch + (size_t)bz * cbatch;
                __nv_bfloat16* dl = Cl + (size_t)bz * cbatch;
                *reinterpret_cast<u32*>(dh + (size_t)r0 * ldc + c0)       = pk(h0, h1);
                *reinterpret_cast<u32*>(dl + (size_t)r0 * ldc + c0)       = pk(l0, l1);
                *reinterpret_cast<u32*>(dh + (size_t)(r0 + 8) * ldc + c0) = pk(h2, h3);
                *reinterpret_cast<u32*>(dl + (size_t)(r0 + 8) * ldc + c0) = pk(l2, l3);
            }
        }
    }
}

// ---------------------------------------------------------------------------
// Prologue: xp = x + pos -> bf16 hi/lo ; weights -> bf16 hi/lo ; packed bias
// ---------------------------------------------------------------------------
__global__ void __launch_bounds__(256) k_prep_x(
    const float4* __restrict__ x, const float4* __restrict__ pos,
    __nv_bfloat16* __restrict__ xh, __nv_bfloat16* __restrict__ xl)
{
    const size_t i = (size_t)blockIdx.x * 256 + threadIdx.x;  // < 2097152
    float4 a = x[i];
    const float4 p = pos[i & 262143u];                        // (S_*D_/4)-1
    a.x += p.x; a.y += p.y; a.z += p.z; a.w += p.w;
    __nv_bfloat16 h0,l0,h1,l1,h2,l2,h3,l3;
    split_bf(a.x,h0,l0); split_bf(a.y,h1,l1); split_bf(a.z,h2,l2); split_bf(a.w,h3,l3);
    *reinterpret_cast<uint2*>(xh + i*4) = make_uint2(pk(h0,h1), pk(h2,h3));
    *reinterpret_cast<uint2*>(xl + i*4) = make_uint2(pk(l0,l1), pk(l2,l3));
}

__global__ void __launch_bounds__(256) k_prep_w(
    const float4* __restrict__ Wq, const float4* __restrict__ Wk,
    const float4* __restrict__ Wv, const float4* __restrict__ Wd,
    const float* __restrict__ bq, const float* __restrict__ bk,
    const float* __restrict__ bv,
    __nv_bfloat16* __restrict__ wh, __nv_bfloat16* __restrict__ wl,
    float* __restrict__ bias)
{
    const int w = blockIdx.y;
    const float4* src = (w == 0) ? Wq : (w == 1) ? Wk : (w == 2) ? Wv : Wd;
    const size_t i = (size_t)blockIdx.x * 256 + threadIdx.x;  // < 65536
    const float4 a = src[i];
    __nv_bfloat16 h0,l0,h1,l1,h2,l2,h3,l3;
    split_bf(a.x,h0,l0); split_bf(a.y,h1,l1); split_bf(a.z,h2,l2); split_bf(a.w,h3,l3);
    const size_t o = (size_t)w * 262144 + i * 4;
    *reinterpret_cast<uint2*>(wh + o) = make_uint2(pk(h0,h1), pk(h2,h3));
    *reinterpret_cast<uint2*>(wl + o) = make_uint2(pk(l0,l1), pk(l2,l3));
    // packed bias (first 512 threads of the first x-block per w<3)
    if (w < 3 && blockIdx.x < 2) {
        const int j = blockIdx.x * 256 + threadIdx.x;         // 0..511
        const float* bsrc = (w == 0) ? bq : (w == 1) ? bk : bv;
        bias[w * 512 + j] = bsrc[j];
    }
}

// ---------------------------------------------------------------------------
// Row softmax over 2048; outputs attn split into bf16 hi/lo
// ---------------------------------------------------------------------------
__global__ void __launch_bounds__(256) k_softmax(
    const float* __restrict__ s,
    __nv_bfloat16* __restrict__ ah, __nv_bfloat16* __restrict__ al)
{
    const size_t base = (size_t)blockIdx.x * S_;
    const float* p = s + base;
    const int tid = threadIdx.x;
    __shared__ float red[8];

    float v[8];
    float mx = -3.4e38f;
#pragma unroll
    for (int i = 0; i < 8; ++i) { v[i] = p[tid + 256 * i]; mx = fmaxf(mx, v[i]); }
#pragma unroll
    for (int o = 16; o > 0; o >>= 1)
        mx = fmaxf(mx, __shfl_xor_sync(0xffffffffu, mx, o));
    if ((tid & 31) == 0) red[tid >> 5] = mx;
    __syncthreads();
    mx = red[0];
#pragma unroll
    for (int w = 1; w < 8; ++w) mx = fmaxf(mx, red[w]);

    float sum = 0.f;
#pragma unroll
    for (int i = 0; i < 8; ++i) { v[i] = expf(v[i] - mx); sum += v[i]; }
#pragma unroll
    for (int o = 16; o > 0; o >>= 1)
        sum += __shfl_xor_sync(0xffffffffu, sum, o);
    __syncthreads();
    if ((tid & 31) == 0) red[tid >> 5] = sum;
    __syncthreads();
    float tot = 0.f;
#pragma unroll
    for (int w = 0; w < 8; ++w) tot += red[w];
    const float inv = 1.0f / tot;

#pragma unroll
    for (int i = 0; i < 8; ++i) {
        const float q = v[i] * inv;
        __nv_bfloat16 h, l;
        split_bf(q, h, l);
        ah[base + tid + 256 * i] = h;
        al[base + tid + 256 * i] = l;
    }
}

// ---------------------------------------------------------------------------
// Launch
// ---------------------------------------------------------------------------
extern "C" void kernel_launch(void* const* d_in, const int* in_sizes, int n_in,
                              void* d_out, int out_size)
{
    const float* x   = (const float*)d_in[0];
    const float* pos = (const float*)d_in[1];
    const float* Wq  = (const float*)d_in[2];
    const float* bq  = (const float*)d_in[3];
    const float* Wk  = (const float*)d_in[4];
    const float* bk  = (const float*)d_in[5];
    const float* Wv  = (const float*)d_in[6];
    const float* bv  = (const float*)d_in[7];
    const float* Wd  = (const float*)d_in[8];
    const float* bd  = (const float*)d_in[9];
    float* out = (float*)d_out;

    __nv_bfloat16 *xh,*xl,*wh,*wl,*qkvh,*qkvl,*yh,*yl,*ah,*al;
    float *sc, *bias;
    cudaGetSymbolAddress((void**)&xh,   g_xh);   cudaGetSymbolAddress((void**)&xl,   g_xl);
    cudaGetSymbolAddress((void**)&wh,   g_wh);   cudaGetSymbolAddress((void**)&wl,   g_wl);
    cudaGetSymbolAddress((void**)&qkvh, g_qkvh); cudaGetSymbolAddress((void**)&qkvl, g_qkvl);
    cudaGetSymbolAddress((void**)&yh,   g_yh);   cudaGetSymbolAddress((void**)&yl,   g_yl);
    cudaGetSymbolAddress((void**)&ah,   g_ah);   cudaGetSymbolAddress((void**)&al,   g_al);
    cudaGetSymbolAddress((void**)&sc,   g_s);    cudaGetSymbolAddress((void**)&bias, g_bias);

    cudaFuncSetAttribute(gemm_k<true,0>,  cudaFuncAttributeMaxDynamicSharedMemorySize, SMEM_DYN);
    cudaFuncSetAttribute(gemm_k<true,1>,  cudaFuncAttributeMaxDynamicSharedMemorySize, SMEM_DYN);
    cudaFuncSetAttribute(gemm_k<false,1>, cudaFuncAttributeMaxDynamicSharedMemorySize, SMEM_DYN);

    const size_t SQ = (size_t)S_ * QKVW;  // batch stride in qkv buffer
    const size_t SS = (size_t)S_ * S_;    // 4194304
    const size_t SD = (size_t)S_ * D_;    // 1048576
    const size_t WW = (size_t)D_ * D_;    // 262144
    const float scale = 0.044194173824159216f;  // 1/sqrt(512)

    k_prep_x<<<8192, 256>>>((const float4*)x, (const float4*)pos, xh, xl);
    k_prep_w<<<dim3(256, 4), 256>>>((const float4*)Wq, (const float4*)Wk,
                                    (const float4*)Wv, (const float4*)Wd,
                                    bq, bk, bv, wh, wl, bias);

    // qkv = xp @ [Wq|Wk|Wv]^T + [bq|bk|bv]   (fused, split hi/lo, ldc=1536)
    gemm_k<true,1><<<dim3(QKVW/TN, NROWS/TM, 1), 256, SMEM_DYN>>>(
        xh, xl, D_, 0, wh, wl, D_, 0, D_, 1.f, bias,
        nullptr, qkvh, qkvl, QKVW, 0);

    // scores = scale * q @ k^T   (fp32); q at col 0, k at col 512 of qkv
    gemm_k<true,0><<<dim3(S_/TN, S_/TM, B_), 256, SMEM_DYN>>>(
        qkvh, qkvl, QKVW, SQ, qkvh + 512, qkvl + 512, QKVW, SQ,
        D_, scale, nullptr, sc, nullptr, nullptr, S_, SS);

    // softmax -> attn hi/lo
    k_softmax<<<B_ * S_, 256>>>(sc, ah, al);

    // y = attn @ v   (NN gemm via ldmatrix.trans); v at col 1024 of qkv
    gemm_k<false,1><<<dim3(D_/TN, S_/TM, B_), 256, SMEM_DYN>>>(
        ah, al, S_, SS, qkvh + 1024, qkvl + 1024, QKVW, SQ,
        S_, 1.f, nullptr, nullptr, yh, yl, D_, SD);

    // out = y @ Wd^T + bd   (fp32)
    gemm_k<true,0><<<dim3(D_/TN, NROWS/TM, 1), 256, SMEM_DYN>>>(
        yh, yl, D_, 0, wh + 3*WW, wl + 3*WW, D_, 0, D_, 1.f, bd,
        out, nullptr, nullptr, D_, 0);
}

// round 8
// speedup vs baseline: 1.1942x; 1.1942x over previous
#include <cuda_runtime.h>
#include <cuda_bf16.h>
#include <stdint.h>

typedef unsigned int u32;

#define B_    8
#define S_    2048
#define D_    512
#define NROWS 16384
#define QKVW  1536              // fused q|k|v row width

// Tiling
#define TM 64
#define TN 128
#define TK 32

// SMEM layout (bytes), XOR-swizzled, no padding
#define AOFF_LO   4096          // A: 64 rows * 64B
#define BOFF_HI   8192
#define B_BUF     8192          // NT: 128 rows * 64B ; NN: 32 rows * 256B
#define STAGE_SZ  24576         // Ah, Al, Bh, Bl
#define NSTAGE    3
#define SMEM_DYN  (NSTAGE*STAGE_SZ)   // 73728 -> 3 CTAs/SM

// ---------------------------------------------------------------------------
// Scratch (static device globals — no runtime allocation)
// ---------------------------------------------------------------------------
__device__ __nv_bfloat16 g_xh[(size_t)NROWS*D_];
__device__ __nv_bfloat16 g_xl[(size_t)NROWS*D_];
__device__ __nv_bfloat16 g_wh[(size_t)4*D_*D_];   // Wq|Wk|Wv|Wd rows
__device__ __nv_bfloat16 g_wl[(size_t)4*D_*D_];
__device__ float         g_bias[QKVW];            // bq|bk|bv packed
__device__ __nv_bfloat16 g_qkvh[(size_t)NROWS*QKVW];
__device__ __nv_bfloat16 g_qkvl[(size_t)NROWS*QKVW];
__device__ __nv_bfloat16 g_yh[(size_t)NROWS*D_];
__device__ __nv_bfloat16 g_yl[(size_t)NROWS*D_];
__device__ float         g_s [(size_t)B_*S_*S_];  // fp32 scores
__device__ __nv_bfloat16 g_ah[(size_t)B_*S_*S_];  // attn hi
__device__ __nv_bfloat16 g_al[(size_t)B_*S_*S_];  // attn lo

// ---------------------------------------------------------------------------
// PTX helpers (portable sm_80-era; legal on base compute_103 target)
// ---------------------------------------------------------------------------
static __device__ __forceinline__ void cpa(u32 dst, const void* src) {
    asm volatile("cp.async.cg.shared.global [%0], [%1], 16;"
                 :: "r"(dst), "l"(src));
}
static __device__ __forceinline__ void ldsm4(u32 &r0,u32 &r1,u32 &r2,u32 &r3, u32 a) {
    asm volatile("ldmatrix.sync.aligned.m8n8.x4.shared.b16 {%0,%1,%2,%3}, [%4];"
                 : "=r"(r0),"=r"(r1),"=r"(r2),"=r"(r3) : "r"(a));
}
static __device__ __forceinline__ void ldsm4t(u32 &r0,u32 &r1,u32 &r2,u32 &r3, u32 a) {
    asm volatile("ldmatrix.sync.aligned.m8n8.x4.trans.shared.b16 {%0,%1,%2,%3}, [%4];"
                 : "=r"(r0),"=r"(r1),"=r"(r2),"=r"(r3) : "r"(a));
}
static __device__ __forceinline__ void mma16816(float* d, const u32* a, const u32* b) {
    asm volatile(
        "mma.sync.aligned.m16n8k16.row.col.f32.bf16.bf16.f32 "
        "{%0,%1,%2,%3}, {%4,%5,%6,%7}, {%8,%9}, {%0,%1,%2,%3};"
        : "+f"(d[0]),"+f"(d[1]),"+f"(d[2]),"+f"(d[3])
        : "r"(a[0]),"r"(a[1]),"r"(a[2]),"r"(a[3]), "r"(b[0]),"r"(b[1]));
}

static __device__ __forceinline__ void split_bf(float x, __nv_bfloat16& h, __nv_bfloat16& l) {
    h = __float2bfloat16(x);
    l = __float2bfloat16(x - __bfloat162float(h));
}
static __device__ __forceinline__ u32 pk(__nv_bfloat16 a, __nv_bfloat16 b) {
    return (u32)__bfloat16_as_ushort(a) | ((u32)__bfloat16_as_ushort(b) << 16);
}

// 64B-row swizzle: logical 16B chunk c of row r -> physical chunk c ^ ((r>>1)&3)
static __device__ __forceinline__ u32 sw64(u32 r, u32 c) {
    return r * 64 + ((c ^ ((r >> 1) & 3)) << 4);
}
// 256B-row swizzle (NN B): chunk c of row r -> c ^ (r&7)
static __device__ __forceinline__ u32 sw256(u32 r, u32 c) {
    return r * 256 + ((c ^ (r & 7)) << 4);
}

// ---------------------------------------------------------------------------
// bf16x3 HMMA GEMM:  C[m,n] = alpha * sum_k A[m,k]*B(n,k)  (+bias[n])
//   A: [M,K] K-major hi/lo.
//   BNK=true : B is [N,K] K-major (NT gemm) ; BNK=false: B is [K,N] (NN gemm)
//   EPI 0: fp32 out (alpha, optional bias);  EPI 1: split bf16 hi/lo out.
// grid = (N/TN, M/TM, batch), 256 threads, 3 CTAs/SM, 3-stage pipeline.
// ---------------------------------------------------------------------------
template <bool BNK, int EPI>
__global__ void __launch_bounds__(256, 3) gemm_k(
    const __nv_bfloat16* __restrict__ Ah, const __nv_bfloat16* __restrict__ Al,
    int lda, size_t abatch,
    const __nv_bfloat16* __restrict__ Bh, const __nv_bfloat16* __restrict__ Bl,
    int ldb, size_t bbatch,
    int K, float alpha, const float* __restrict__ bias,
    float* __restrict__ Cf, __nv_bfloat16* __restrict__ Ch, __nv_bfloat16* __restrict__ Cl,
    int ldc, size_t cbatch)
{
    extern __shared__ __align__(1024) char dsm[];
    const u32 sb   = (u32)__cvta_generic_to_shared(dsm);
    const int tid  = threadIdx.x;
    const int wid  = tid >> 5;
    const int lane = tid & 31;
    const int bm = blockIdx.y, bn = blockIdx.x, bz = blockIdx.z;
    const int warp_m = wid & 1;        // 2 warps along M (32 rows each)
    const int warp_n = wid >> 1;       // 4 warps along N (32 cols each)

    const __nv_bfloat16* pAh = Ah + (size_t)bz*abatch + (size_t)(bm*TM)*lda;
    const __nv_bfloat16* pAl = Al + (size_t)bz*abatch + (size_t)(bm*TM)*lda;
    const __nv_bfloat16* pBh;
    const __nv_bfloat16* pBl;
    if (BNK) {
        pBh = Bh + (size_t)bz*bbatch + (size_t)(bn*TN)*ldb;
        pBl = Bl + (size_t)bz*bbatch + (size_t)(bn*TN)*ldb;
    } else {
        pBh = Bh + (size_t)bz*bbatch + bn*TN;
        pBl = Bl + (size_t)bz*bbatch + bn*TN;
    }

    // ---- stage loader: 6 cp.async (16B) per thread, swizzled dst ----
    auto load_stage = [&](int stg, int t) {
        const int k0 = t * TK;
        const u32 da = sb + stg * STAGE_SZ;
        {   // A: 64 rows x 4 chunks
            const u32 r = (u32)tid >> 2, c = (u32)tid & 3;
            const u32 d = da + sw64(r, c);
            cpa(d,           pAh + (size_t)r * lda + k0 + c * 8);
            cpa(d + AOFF_LO, pAl + (size_t)r * lda + k0 + c * 8);
        }
#pragma unroll
        for (int i = 0; i < 2; ++i) {
            const u32 idx = (u32)tid + i * 256;
            if (BNK) {
                const u32 r = idx >> 2, c = idx & 3;        // 128 rows x 4 chunks
                const u32 db = da + BOFF_HI + sw64(r, c);
                cpa(db,         pBh + (size_t)r * ldb + k0 + c * 8);
                cpa(db + B_BUF, pBl + (size_t)r * ldb + k0 + c * 8);
            } else {
                const u32 r = idx >> 4, c = idx & 15;       // 32 rows x 16 chunks
                const u32 db = da + BOFF_HI + sw256(r, c);
                cpa(db,         pBh + (size_t)(k0 + r) * ldb + c * 8);
                cpa(db + B_BUF, pBl + (size_t)(k0 + r) * ldb + c * 8);
            }
        }
        asm volatile("cp.async.commit_group;");
    };

    // ---- per-warp fragment address components ----
    // A: row = warp_m*32 + mt*16 + (lane&15); chunk = kk*2 + (lane>>4)
    u32 a_row[2], a_key[2];
#pragma unroll
    for (int mt = 0; mt < 2; ++mt) {
        const u32 r = warp_m * 32 + mt * 16 + (lane & 15);
        a_row[mt] = r * 64;
        a_key[mt] = (r >> 1) & 3;
    }
    const u32 a_ch = (u32)(lane >> 4);
    // B NT: row = warp_n*32 + n2*16 + ((lane>>4)&1)*8 + (lane&7); chunk = kk*2 + ((lane>>3)&1)
    u32 b_row[2], b_key[2];
#pragma unroll
    for (int n2 = 0; n2 < 2; ++n2) {
        const u32 r = warp_n * 32 + n2 * 16 + ((lane >> 4) & 1) * 8 + (lane & 7);
        b_row[n2] = r * 64;
        b_key[n2] = (r >> 1) & 3;
    }
    const u32 b_ch = (u32)((lane >> 3) & 1);
    // B NN: row = kk*16 + rpart; chunk = warp_n*4 + ((lane>>4)&1) + 2*n2; key = rpart&7
    const u32 nn_rpart = ((lane >> 3) & 1) * 8 + (lane & 7);
    const u32 nn_c0    = warp_n * 4 + ((lane >> 4) & 1);
    const u32 nn_key   = (u32)(lane & 7);

    float acc[2][4][4];
#pragma unroll
    for (int mt = 0; mt < 2; ++mt)
#pragma unroll
        for (int nt = 0; nt < 4; ++nt)
#pragma unroll
            for (int i = 0; i < 4; ++i) acc[mt][nt][i] = 0.f;

    // ---- compute one stage (2 k16 steps, hh -> hl -> lh) ----
    auto compute = [&](int stg) {
        const u32 sa = sb + stg * STAGE_SZ;
#pragma unroll
        for (int kk = 0; kk < 2; ++kk) {
            u32 ahf[2][4], bhf[4][2], blf[4][2], alf[2][4];
            const u32 ca = kk * 2 + a_ch;
            const u32 cb = kk * 2 + b_ch;
#pragma unroll
            for (int mt = 0; mt < 2; ++mt)
                ldsm4(ahf[mt][0], ahf[mt][1], ahf[mt][2], ahf[mt][3],
                      sa + a_row[mt] + ((ca ^ a_key[mt]) << 4));
#pragma unroll
            for (int n2 = 0; n2 < 2; ++n2) {
                u32 r0, r1, r2, r3;
                if (BNK)
                    ldsm4(r0, r1, r2, r3,
                          sa + BOFF_HI + b_row[n2] + ((cb ^ b_key[n2]) << 4));
                else
                    ldsm4t(r0, r1, r2, r3,
                           sa + BOFF_HI + sw256(kk * 16 + nn_rpart, nn_c0 + 2 * n2));
                bhf[n2*2][0] = r0; bhf[n2*2][1] = r1;
                bhf[n2*2+1][0] = r2; bhf[n2*2+1][1] = r3;
            }
#pragma unroll
            for (int mt = 0; mt < 2; ++mt)
#pragma unroll
                for (int nt = 0; nt < 4; ++nt)
                    mma16816(acc[mt][nt], ahf[mt], bhf[nt]);      // hi*hi

#pragma unroll
            for (int n2 = 0; n2 < 2; ++n2) {
                u32 r0, r1, r2, r3;
                if (BNK)
                    ldsm4(r0, r1, r2, r3,
                          sa + BOFF_HI + B_BUF + b_row[n2] + ((cb ^ b_key[n2]) << 4));
                else
                    ldsm4t(r0, r1, r2, r3,
                           sa + BOFF_HI + B_BUF + sw256(kk * 16 + nn_rpart, nn_c0 + 2 * n2));
                blf[n2*2][0] = r0; blf[n2*2][1] = r1;
                blf[n2*2+1][0] = r2; blf[n2*2+1][1] = r3;
            }
#pragma unroll
            for (int mt = 0; mt < 2; ++mt)
#pragma unroll
                for (int nt = 0; nt < 4; ++nt)
                    mma16816(acc[mt][nt], ahf[mt], blf[nt]);      // hi*lo

#pragma unroll
            for (int mt = 0; mt < 2; ++mt)
                ldsm4(alf[mt][0], alf[mt][1], alf[mt][2], alf[mt][3],
                      sa + AOFF_LO + a_row[mt] + ((ca ^ a_key[mt]) << 4));
#pragma unroll
            for (int mt = 0; mt < 2; ++mt)
#pragma unroll
                for (int nt = 0; nt < 4; ++nt)
                    mma16816(acc[mt][nt], alf[mt], bhf[nt]);      // lo*hi
        }
    };

    // ---- 3-stage mainloop, one barrier per k-tile ----
    const int T = K / TK;
    load_stage(0, 0);
    if (T > 1) load_stage(1, 1);
    int s_cmp = 0, s_ld = 2;
    for (int t = 0; t < T; ++t) {
        if (t + 2 < T) asm volatile("cp.async.wait_group 1;");
        else           asm volatile("cp.async.wait_group 0;");
        __syncthreads();
        if (t + 2 < T) {
            load_stage(s_ld, t + 2);
            if (++s_ld == NSTAGE) s_ld = 0;
        }
        compute(s_cmp);
        if (++s_cmp == NSTAGE) s_cmp = 0;
    }

    // ---- epilogue ----
    const int g  = lane >> 2;
    const int tc = lane & 3;
    const int row_w = bm * TM + warp_m * 32;
    const int col_w = bn * TN + warp_n * 32;
#pragma unroll
    for (int mt = 0; mt < 2; ++mt) {
#pragma unroll
        for (int nt = 0; nt < 4; ++nt) {
            const int r0 = row_w + mt * 16 + g;
            const int c0 = col_w + nt * 8 + tc * 2;
            float v0 = acc[mt][nt][0], v1 = acc[mt][nt][1];
            float v2 = acc[mt][nt][2], v3 = acc[mt][nt][3];
            if constexpr (EPI == 0) {
                v0 *= alpha; v1 *= alpha; v2 *= alpha; v3 *= alpha;
                if (bias) {
                    const float b0 = bias[c0], b1 = bias[c0 + 1];
                    v0 += b0; v1 += b1; v2 += b0; v3 += b1;
                }
                float* base = Cf + (size_t)bz * cbatch;
                *reinterpret_cast<float2*>(base + (size_t)r0 * ldc + c0)       = make_float2(v0, v1);
                *reinterpret_cast<float2*>(base + (size_t)(r0 + 8) * ldc + c0) = make_float2(v2, v3);
            } else {
                if (bias) {
                    const float b0 = bias[c0], b1 = bias[c0 + 1];
                    v0 += b0; v1 += b1; v2 += b0; v3 += b1;
                }
                __nv_bfloat16 h0,l0,h1,l1,h2,l2,h3,l3;
                split_bf(v0,h0,l0); split_bf(v1,h1,l1);
                split_bf(v2,h2,l2); split_bf(v3,h3,l3);
                __nv_bfloat16* dh = Ch + (size_t)bz * cbatch;
                __nv_bfloat16* dl = Cl + (size_t)bz * cbatch;
                *reinterpret_cast<u32*>(dh + (size_t)r0 * ldc + c0)       = pk(h0, h1);
                *reinterpret_cast<u32*>(dl + (size_t)r0 * ldc + c0)       = pk(l0, l1);
                *reinterpret_cast<u32*>(dh + (size_t)(r0 + 8) * ldc + c0) = pk(h2, h3);
                *reinterpret_cast<u32*>(dl + (size_t)(r0 + 8) * ldc + c0) = pk(l2, l3);
            }
        }
    }
}

// ---------------------------------------------------------------------------
// Prologue: xp = x + pos -> bf16 hi/lo ; weights -> bf16 hi/lo ; packed bias
// ---------------------------------------------------------------------------
__global__ void __launch_bounds__(256) k_prep_x(
    const float4* __restrict__ x, const float4* __restrict__ pos,
    __nv_bfloat16* __restrict__ xh, __nv_bfloat16* __restrict__ xl)
{
    const size_t i = (size_t)blockIdx.x * 256 + threadIdx.x;  // < 2097152
    float4 a = x[i];
    const float4 p = pos[i & 262143u];                        // (S_*D_/4)-1
    a.x += p.x; a.y += p.y; a.z += p.z; a.w += p.w;
    __nv_bfloat16 h0,l0,h1,l1,h2,l2,h3,l3;
    split_bf(a.x,h0,l0); split_bf(a.y,h1,l1); split_bf(a.z,h2,l2); split_bf(a.w,h3,l3);
    *reinterpret_cast<uint2*>(xh + i*4) = make_uint2(pk(h0,h1), pk(h2,h3));
    *reinterpret_cast<uint2*>(xl + i*4) = make_uint2(pk(l0,l1), pk(l2,l3));
}

__global__ void __launch_bounds__(256) k_prep_w(
    const float4* __restrict__ Wq, const float4* __restrict__ Wk,
    const float4* __restrict__ Wv, const float4* __restrict__ Wd,
    const float* __restrict__ bq, const float* __restrict__ bk,
    const float* __restrict__ bv,
    __nv_bfloat16* __restrict__ wh, __nv_bfloat16* __restrict__ wl,
    float* __restrict__ bias)
{
    const int w = blockIdx.y;
    const float4* src = (w == 0) ? Wq : (w == 1) ? Wk : (w == 2) ? Wv : Wd;
    const size_t i = (size_t)blockIdx.x * 256 + threadIdx.x;  // < 65536
    const float4 a = src[i];
    __nv_bfloat16 h0,l0,h1,l1,h2,l2,h3,l3;
    split_bf(a.x,h0,l0); split_bf(a.y,h1,l1); split_bf(a.z,h2,l2); split_bf(a.w,h3,l3);
    const size_t o = (size_t)w * 262144 + i * 4;
    *reinterpret_cast<uint2*>(wh + o) = make_uint2(pk(h0,h1), pk(h2,h3));
    *reinterpret_cast<uint2*>(wl + o) = make_uint2(pk(l0,l1), pk(l2,l3));
    if (w < 3 && blockIdx.x < 2) {
        const int j = blockIdx.x * 256 + threadIdx.x;         // 0..511
        const float* bsrc = (w == 0) ? bq : (w == 1) ? bk : bv;
        bias[w * 512 + j] = bsrc[j];
    }
}

// ---------------------------------------------------------------------------
// Row softmax over 2048; outputs attn split into bf16 hi/lo
// ---------------------------------------------------------------------------
__global__ void __launch_bounds__(256) k_softmax(
    const float* __restrict__ s,
    __nv_bfloat16* __restrict__ ah, __nv_bfloat16* __restrict__ al)
{
    const size_t base = (size_t)blockIdx.x * S_;
    const float* p = s + base;
    const int tid = threadIdx.x;
    __shared__ float red[8];

    float v[8];
    float mx = -3.4e38f;
#pragma unroll
    for (int i = 0; i < 8; ++i) { v[i] = p[tid + 256 * i]; mx = fmaxf(mx, v[i]); }
#pragma unroll
    for (int o = 16; o > 0; o >>= 1)
        mx = fmaxf(mx, __shfl_xor_sync(0xffffffffu, mx, o));
    if ((tid & 31) == 0) red[tid >> 5] = mx;
    __syncthreads();
    mx = red[0];
#pragma unroll
    for (int w = 1; w < 8; ++w) mx = fmaxf(mx, red[w]);

    float sum = 0.f;
#pragma unroll
    for (int i = 0; i < 8; ++i) { v[i] = expf(v[i] - mx); sum += v[i]; }
#pragma unroll
    for (int o = 16; o > 0; o >>= 1)
        sum += __shfl_xor_sync(0xffffffffu, sum, o);
    __syncthreads();
    if ((tid & 31) == 0) red[tid >> 5] = sum;
    __syncthreads();
    float tot = 0.f;
#pragma unroll
    for (int w = 0; w < 8; ++w) tot += red[w];
    const float inv = 1.0f / tot;

#pragma unroll
    for (int i = 0; i < 8; ++i) {
        const float q = v[i] * inv;
        __nv_bfloat16 h, l;
        split_bf(q, h, l);
        ah[base + tid + 256 * i] = h;
        al[base + tid + 256 * i] = l;
    }
}

// ---------------------------------------------------------------------------
// Launch
// ---------------------------------------------------------------------------
extern "C" void kernel_launch(void* const* d_in, const int* in_sizes, int n_in,
                              void* d_out, int out_size)
{
    const float* x   = (const float*)d_in[0];
    const float* pos = (const float*)d_in[1];
    const float* Wq  = (const float*)d_in[2];
    const float* bq  = (const float*)d_in[3];
    const float* Wk  = (const float*)d_in[4];
    const float* bk  = (const float*)d_in[5];
    const float* Wv  = (const float*)d_in[6];
    const float* bv  = (const float*)d_in[7];
    const float* Wd  = (const float*)d_in[8];
    const float* bd  = (const float*)d_in[9];
    float* out = (float*)d_out;

    __nv_bfloat16 *xh,*xl,*wh,*wl,*qkvh,*qkvl,*yh,*yl,*ah,*al;
    float *sc, *bias;
    cudaGetSymbolAddress((void**)&xh,   g_xh);   cudaGetSymbolAddress((void**)&xl,   g_xl);
    cudaGetSymbolAddress((void**)&wh,   g_wh);   cudaGetSymbolAddress((void**)&wl,   g_wl);
    cudaGetSymbolAddress((void**)&qkvh, g_qkvh); cudaGetSymbolAddress((void**)&qkvl, g_qkvl);
    cudaGetSymbolAddress((void**)&yh,   g_yh);   cudaGetSymbolAddress((void**)&yl,   g_yl);
    cudaGetSymbolAddress((void**)&ah,   g_ah);   cudaGetSymbolAddress((void**)&al,   g_al);
    cudaGetSymbolAddress((void**)&sc,   g_s);    cudaGetSymbolAddress((void**)&bias, g_bias);

    cudaFuncSetAttribute(gemm_k<true,0>,  cudaFuncAttributeMaxDynamicSharedMemorySize, SMEM_DYN);
    cudaFuncSetAttribute(gemm_k<true,1>,  cudaFuncAttributeMaxDynamicSharedMemorySize, SMEM_DYN);
    cudaFuncSetAttribute(gemm_k<false,1>, cudaFuncAttributeMaxDynamicSharedMemorySize, SMEM_DYN);

    const size_t SQ = (size_t)S_ * QKVW;  // batch stride in qkv buffer
    const size_t SS = (size_t)S_ * S_;    // 4194304
    const size_t SD = (size_t)S_ * D_;    // 1048576
    const size_t WW = (size_t)D_ * D_;    // 262144
    const float scale = 0.044194173824159216f;  // 1/sqrt(512)

    k_prep_x<<<8192, 256>>>((const float4*)x, (const float4*)pos, xh, xl);
    k_prep_w<<<dim3(256, 4), 256>>>((const float4*)Wq, (const float4*)Wk,
                                    (const float4*)Wv, (const float4*)Wd,
                                    bq, bk, bv, wh, wl, bias);

    // qkv = xp @ [Wq|Wk|Wv]^T + [bq|bk|bv]   (fused, split hi/lo, ldc=1536)
    gemm_k<true,1><<<dim3(QKVW/TN, NROWS/TM, 1), 256, SMEM_DYN>>>(
        xh, xl, D_, 0, wh, wl, D_, 0, D_, 1.f, bias,
        nullptr, qkvh, qkvl, QKVW, 0);

    // scores = scale * q @ k^T   (fp32); q at col 0, k at col 512 of qkv
    gemm_k<true,0><<<dim3(S_/TN, S_/TM, B_), 256, SMEM_DYN>>>(
        qkvh, qkvl, QKVW, SQ, qkvh + 512, qkvl + 512, QKVW, SQ,
        D_, scale, nullptr, sc, nullptr, nullptr, S_, SS);

    // softmax -> attn hi/lo
    k_softmax<<<B_ * S_, 256>>>(sc, ah, al);

    // y = attn @ v   (NN gemm via ldmatrix.trans); v at col 1024 of qkv
    gemm_k<false,1><<<dim3(D_/TN, S_/TM, B_), 256, SMEM_DYN>>>(
        ah, al, S_, SS, qkvh + 1024, qkvl + 1024, QKVW, SQ,
        S_, 1.f, nullptr, nullptr, yh, yl, D_, SD);

    // out = y @ Wd^T + bd   (fp32)
    gemm_k<true,0><<<dim3(D_/TN, NROWS/TM, 1), 256, SMEM_DYN>>>(
        yh, yl, D_, 0, wh + 3*WW, wl + 3*WW, D_, 0, D_, 1.f, bd,
        out, nullptr, nullptr, D_, 0);
}